// round 1
// baseline (speedup 1.0000x reference)
#include <cuda_runtime.h>
#include <math.h>

#define BB 8
#define TT 2048
#define II 1024
#define HH 1024
#define G4 4096
#define OO 4096

// ---------------- scratch (no allocations allowed) ----------------
__device__ float g_xg[(size_t)BB * TT * G4];   // [b][t][4H] input-gate precompute, 268 MB
__device__ float g_h[2][HH * BB];              // double-buffered hidden state, layout [k*8 + b]
__device__ unsigned int g_bar_count = 0;
__device__ volatile unsigned int g_bar_sense = 0;

// =================================================================
// Kernel 1: xg[m][n] = sum_k x[m][k] * W_ih[n][k] + (b_ih[n]+b_hh[n])
//   M = B*T = 16384, N = 4H = 4096, K = 1024. Both operands K-major (NT).
// =================================================================
#define BM 128
#define BN 64
#define BKK 16

__global__ __launch_bounds__(256) void gemm_xg_kernel(
    const float* __restrict__ x, const float* __restrict__ Wih,
    const float* __restrict__ bih, const float* __restrict__ bhh)
{
    __shared__ float As[BKK][BM];
    __shared__ float Ws[BKK][BN];
    const int tid = threadIdx.x;
    const int m0 = blockIdx.y * BM;
    const int n0 = blockIdx.x * BN;
    const int tx = tid & 15;   // 16 threads * TN=4 -> 64 cols
    const int ty = tid >> 4;   // 16 threads * TM=8 -> 128 rows

    float acc[8][4];
#pragma unroll
    for (int i = 0; i < 8; i++)
#pragma unroll
        for (int j = 0; j < 4; j++) acc[i][j] = 0.f;

    for (int k0 = 0; k0 < II; k0 += BKK) {
        // Load A tile (128 x 16): 512 float4, 2 per thread, transpose into As[k][m]
#pragma unroll
        for (int r = 0; r < 2; r++) {
            int f = tid + r * 256;
            int m = f >> 2, kq = f & 3;
            float4 v = *(const float4*)&x[(size_t)(m0 + m) * II + k0 + kq * 4];
            As[kq * 4 + 0][m] = v.x;
            As[kq * 4 + 1][m] = v.y;
            As[kq * 4 + 2][m] = v.z;
            As[kq * 4 + 3][m] = v.w;
        }
        // Load W tile (64 x 16): 256 float4, 1 per thread
        {
            int f = tid;
            int n = f >> 2, kq = f & 3;
            float4 v = *(const float4*)&Wih[(size_t)(n0 + n) * II + k0 + kq * 4];
            Ws[kq * 4 + 0][n] = v.x;
            Ws[kq * 4 + 1][n] = v.y;
            Ws[kq * 4 + 2][n] = v.z;
            Ws[kq * 4 + 3][n] = v.w;
        }
        __syncthreads();
#pragma unroll
        for (int kk = 0; kk < BKK; kk++) {
            float a[8], w[4];
#pragma unroll
            for (int i = 0; i < 8; i++) a[i] = As[kk][ty * 8 + i];
#pragma unroll
            for (int j = 0; j < 4; j++) w[j] = Ws[kk][tx * 4 + j];
#pragma unroll
            for (int i = 0; i < 8; i++)
#pragma unroll
                for (int j = 0; j < 4; j++) acc[i][j] += a[i] * w[j];
        }
        __syncthreads();
    }

    float bias[4];
#pragma unroll
    for (int j = 0; j < 4; j++) {
        int n = n0 + tx * 4 + j;
        bias[j] = bih[n] + bhh[n];
    }
#pragma unroll
    for (int i = 0; i < 8; i++) {
        int m = m0 + ty * 8 + i;
#pragma unroll
        for (int j = 0; j < 4; j++) {
            g_xg[(size_t)m * G4 + n0 + tx * 4 + j] = acc[i][j] + bias[j];
        }
    }
}

// =================================================================
// Kernel 2: persistent recurrent LSTM kernel.
//   128 CTAs x 256 threads, 1 CTA/SM (all co-resident -> spin barrier safe).
//   CTA s owns h columns [s*8, s*8+8) and the 32 gate rows {q*1024 + col}.
//   W_hh slice (32 rows x 1024) lives in REGISTERS: lane = local gate row,
//   warp = k-chunk of 128 -> 128 weight regs/thread, loaded once.
//   Per step: stage h (L2, __ldcg) -> smem; each lane does 8 dot-partials
//   (all batches, its row, its warp's k-chunk); partials -> smem; 64 threads
//   do the cross-warp reduce + gate nonlinearity + c/h update; one grid
//   barrier (sense = step index, safe across graph replays since the stale
//   final sense never equals target 1 and releases are monotone).
// =================================================================
#define NB 128
#define CPB 8     // h columns per block
#define KC 128    // k elements per warp

__global__ __launch_bounds__(256, 1) void lstm_rec_kernel(const float* __restrict__ Whh)
{
    __shared__ float h_s[HH * BB];          // 32 KB, layout [k*8 + b]
    __shared__ float part[8][32][BB];       // 8 KB  [warp][local row][b]
    __shared__ float c_s[CPB][BB];          // cell state, persistent across steps

    const int tid = threadIdx.x;
    const int w = tid >> 5;
    const int l = tid & 31;                  // local gate row 0..31
    const int c0 = blockIdx.x * CPB;
    const int grow = (l >> 3) * HH + c0 + (l & 7);  // global gate row
    const int kb = w * KC;

    // Load this lane's weight slice into registers (once per launch).
    float wr[KC];
#pragma unroll
    for (int j = 0; j < KC; j++) wr[j] = Whh[(size_t)grow * HH + kb + j];

    if (tid < CPB * BB) c_s[tid >> 3][tid & 7] = 0.f;

    for (int t = 0; t < TT; t++) {
        const int rb = t & 1;
        const int wb = rb ^ 1;

        // ---- stage h into smem (bypass L1: another CTA wrote it) ----
        if (t == 0) {
#pragma unroll
            for (int i = tid; i < HH * BB / 4; i += 256)
                ((float4*)h_s)[i] = make_float4(0.f, 0.f, 0.f, 0.f);
        } else {
#pragma unroll
            for (int i = tid; i < HH * BB / 4; i += 256)
                ((float4*)h_s)[i] = __ldcg(((const float4*)g_h[rb]) + i);
        }
        __syncthreads();

        // ---- partial dot products: row l, k in [kb, kb+128), all 8 batches ----
        float acc[BB];
#pragma unroll
        for (int b = 0; b < BB; b++) acc[b] = 0.f;
#pragma unroll
        for (int j = 0; j < KC; j++) {
            const float4 h0 = *(const float4*)&h_s[(kb + j) * 8];
            const float4 h1 = *(const float4*)&h_s[(kb + j) * 8 + 4];
            const float wv = wr[j];
            acc[0] += wv * h0.x; acc[1] += wv * h0.y;
            acc[2] += wv * h0.z; acc[3] += wv * h0.w;
            acc[4] += wv * h1.x; acc[5] += wv * h1.y;
            acc[6] += wv * h1.z; acc[7] += wv * h1.w;
        }
#pragma unroll
        for (int b = 0; b < BB; b++) part[w][l][b] = acc[b];
        __syncthreads();

        // ---- gate reduce + nonlinearity + state update (64 threads) ----
        if (tid < CPB * BB) {
            const int cc = tid >> 3;
            const int b = tid & 7;
            float gs[4];
#pragma unroll
            for (int q = 0; q < 4; q++) {
                float s = g_xg[((size_t)b * TT + t) * G4 + q * HH + c0 + cc];
#pragma unroll
                for (int ww = 0; ww < 8; ww++) s += part[ww][q * 8 + cc][b];
                gs[q] = s;
            }
            const float ig = 1.f / (1.f + expf(-gs[0]));
            const float fg = 1.f / (1.f + expf(-gs[1]));
            const float gg = tanhf(gs[2]);
            const float og = 1.f / (1.f + expf(-gs[3]));
            const float c = fg * c_s[cc][b] + ig * gg;
            c_s[cc][b] = c;
            const float h = og * tanhf(c);
            g_h[wb][(c0 + cc) * 8 + b] = h;
        }
        __syncthreads();   // all writes of this CTA done before arrival

        // ---- grid-wide sense barrier ----
        if (tid == 0) {
            __threadfence();
            const unsigned int target = (unsigned int)(t + 1);
            if (atomicAdd(&g_bar_count, 1) == NB - 1) {
                g_bar_count = 0;
                __threadfence();
                g_bar_sense = target;
            } else {
                while (g_bar_sense != target) { }
            }
            __threadfence();
        }
        __syncthreads();
    }
}

// =================================================================
// Kernel 3: out[b][o] = sum_k hT[b][k] * W_fc[o][k] + b_fc[o]
//   hT lives in g_h[0] (parity after 2048 steps), layout [k*8+b].
// =================================================================
__global__ __launch_bounds__(256) void fc_kernel(
    const float* __restrict__ Wfc, const float* __restrict__ bfc,
    float* __restrict__ out)
{
    const int o = blockIdx.x;
    const int tid = threadIdx.x;
    float acc[BB];
#pragma unroll
    for (int b = 0; b < BB; b++) acc[b] = 0.f;

    for (int k = tid; k < HH; k += 256) {
        const float wv = Wfc[(size_t)o * HH + k];
#pragma unroll
        for (int b = 0; b < BB; b++) acc[b] += wv * g_h[0][k * 8 + b];
    }
    const int lane = tid & 31, wrp = tid >> 5;
#pragma unroll
    for (int off = 16; off; off >>= 1)
#pragma unroll
        for (int b = 0; b < BB; b++)
            acc[b] += __shfl_down_sync(0xffffffffu, acc[b], off);

    __shared__ float red[8][BB];
    if (lane == 0)
#pragma unroll
        for (int b = 0; b < BB; b++) red[wrp][b] = acc[b];
    __syncthreads();
    if (tid < BB) {
        float s = bfc[o];
#pragma unroll
        for (int ww = 0; ww < 8; ww++) s += red[ww][tid];
        out[(size_t)tid * OO + o] = s;
    }
}

// =================================================================
extern "C" void kernel_launch(void* const* d_in, const int* in_sizes, int n_in,
                              void* d_out, int out_size)
{
    const float* x    = (const float*)d_in[0];   // [8,2048,1024]
    const float* Wih  = (const float*)d_in[1];   // [4096,1024]
    const float* Whh  = (const float*)d_in[2];   // [4096,1024]
    const float* bih  = (const float*)d_in[3];   // [4096]
    const float* bhh  = (const float*)d_in[4];   // [4096]
    const float* Wfc  = (const float*)d_in[5];   // [4096,1024]
    const float* bfc  = (const float*)d_in[6];   // [4096]
    float* out = (float*)d_out;                  // [1,8,4096]

    dim3 g1(G4 / BN, (BB * TT) / BM);            // (64, 128)
    gemm_xg_kernel<<<g1, 256>>>(x, Wih, bih, bhh);
    lstm_rec_kernel<<<NB, 256>>>(Whh);
    fc_kernel<<<OO, 256>>>(Wfc, bfc, out);
    (void)in_sizes; (void)n_in; (void)out_size;
}

// round 2
// speedup vs baseline: 1.1406x; 1.1406x over previous
#include <cuda_runtime.h>
#include <math.h>

#define BB 8
#define TT 2048
#define II 1024
#define HH 1024
#define G4 4096
#define OO 4096

// ---------------- scratch (no allocations allowed) ----------------
__device__ float g_xg[(size_t)BB * TT * G4];   // [b][t][4H] input-gate precompute
__device__ float g_h[2][HH * BB];              // double-buffered h, PAIR layout:
                                               //   (k,b) -> (k>>1)*16 + b*2 + (k&1)
__device__ unsigned int g_bar_count = 0;
__device__ volatile unsigned int g_bar_sense = 0;

// packed f32x2 helpers (sm_103a: fma.rn.f32x2 only reachable via PTX)
#define FMA2(d, a, b) asm("fma.rn.f32x2 %0, %1, %2, %0;" : "+l"(d) : "l"(a), "l"(b))
#define PACK2(d, s)   asm("mov.b64 %0, {%1, %1};" : "=l"(d) : "f"(s))

// =================================================================
// Kernel 1: xg[m][n] = sum_k x[m][k]*W_ih[n][k] + (b_ih[n]+b_hh[n])
//   M=16384, N=4096, K=1024 (NT). 128x128 tile, f32x2 math.
// =================================================================
#define BM 128
#define BN 128
#define BK 16
#define LDP 132   // padded row (floats), keeps 16B alignment, breaks store conflicts

__global__ __launch_bounds__(256) void gemm_xg_kernel(
    const float* __restrict__ x, const float* __restrict__ Wih,
    const float* __restrict__ bih, const float* __restrict__ bhh)
{
    __shared__ float As[BK][LDP];
    __shared__ float Ws[BK][LDP];
    const int tid = threadIdx.x;
    const int m0 = blockIdx.y * BM;
    const int n0 = blockIdx.x * BN;
    const int tx = tid & 15;   // 16 * TN(8) = 128 cols
    const int ty = tid >> 4;   // 16 * TM(8) = 128 rows

    unsigned long long acc[4][8];   // [m-pair][n], each holds (row 2p, row 2p+1)
#pragma unroll
    for (int p = 0; p < 4; p++)
#pragma unroll
        for (int n = 0; n < 8; n++) acc[p][n] = 0ull;

    for (int k0 = 0; k0 < II; k0 += BK) {
        // A tile 128x16 -> transposed As[k][m].  512 float4, 2/thread.
#pragma unroll
        for (int r = 0; r < 2; r++) {
            int f = tid + r * 256;
            int m = f >> 2, kq = f & 3;
            float4 v = *(const float4*)&x[(size_t)(m0 + m) * II + k0 + kq * 4];
            As[kq * 4 + 0][m] = v.x;
            As[kq * 4 + 1][m] = v.y;
            As[kq * 4 + 2][m] = v.z;
            As[kq * 4 + 3][m] = v.w;
        }
        // W tile 128x16 -> transposed Ws[k][n].
#pragma unroll
        for (int r = 0; r < 2; r++) {
            int f = tid + r * 256;
            int n = f >> 2, kq = f & 3;
            float4 v = *(const float4*)&Wih[(size_t)(n0 + n) * II + k0 + kq * 4];
            Ws[kq * 4 + 0][n] = v.x;
            Ws[kq * 4 + 1][n] = v.y;
            Ws[kq * 4 + 2][n] = v.z;
            Ws[kq * 4 + 3][n] = v.w;
        }
        __syncthreads();
#pragma unroll
        for (int kk = 0; kk < BK; kk++) {
            const ulonglong2 a01 = *(const ulonglong2*)&As[kk][ty * 8];
            const ulonglong2 a23 = *(const ulonglong2*)&As[kk][ty * 8 + 4];
            const float4 w0 = *(const float4*)&Ws[kk][tx * 8];
            const float4 w1 = *(const float4*)&Ws[kk][tx * 8 + 4];
            unsigned long long wd[8];
            PACK2(wd[0], w0.x); PACK2(wd[1], w0.y);
            PACK2(wd[2], w0.z); PACK2(wd[3], w0.w);
            PACK2(wd[4], w1.x); PACK2(wd[5], w1.y);
            PACK2(wd[6], w1.z); PACK2(wd[7], w1.w);
#pragma unroll
            for (int n = 0; n < 8; n++) {
                FMA2(acc[0][n], a01.x, wd[n]);
                FMA2(acc[1][n], a01.y, wd[n]);
                FMA2(acc[2][n], a23.x, wd[n]);
                FMA2(acc[3][n], a23.y, wd[n]);
            }
        }
        __syncthreads();
    }

    float bias[8];
#pragma unroll
    for (int n = 0; n < 8; n++) {
        int nn = n0 + tx * 8 + n;
        bias[n] = bih[nn] + bhh[nn];
    }
#pragma unroll
    for (int p = 0; p < 4; p++) {
        float r0[8], r1[8];
#pragma unroll
        for (int n = 0; n < 8; n++) {
            float2 f = *(float2*)&acc[p][n];
            r0[n] = f.x + bias[n];
            r1[n] = f.y + bias[n];
        }
        const size_t m = (size_t)(m0 + ty * 8 + 2 * p);
        float* o0 = &g_xg[m * G4 + n0 + tx * 8];
        float* o1 = o0 + G4;
        *(float4*)o0       = make_float4(r0[0], r0[1], r0[2], r0[3]);
        *((float4*)o0 + 1) = make_float4(r0[4], r0[5], r0[6], r0[7]);
        *(float4*)o1       = make_float4(r1[0], r1[1], r1[2], r1[3]);
        *((float4*)o1 + 1) = make_float4(r1[4], r1[5], r1[6], r1[7]);
    }
}

// =================================================================
// Kernel 2: persistent recurrent LSTM. 128 CTAs x 256 thr, 1 CTA/SM.
//   CTA s owns h cols [s*8, s*8+8). Lane = local gate row (32 rows/CTA),
//   warp = k-chunk of 128. Weights pre-packed over adjacent k into 64
//   b64 regs/lane. h stored (global+smem) in PAIR layout so the dot
//   product is pure LDS.128 + fma.rn.f32x2 with zero repacking.
//   xg gate biases prefetched at step top to hide DRAM latency.
// =================================================================
#define NB 128
#define CPB 8     // h columns per block
#define KC 128    // k elements per warp

__global__ __launch_bounds__(256, 1) void lstm_rec_kernel(const float* __restrict__ Whh)
{
    __shared__ float h_s[HH * BB];          // 32 KB, pair layout
    __shared__ float part[8][32][BB];       // [warp][local row][b]
    __shared__ float c_s[CPB][BB];          // cell state

    const int tid = threadIdx.x;
    const int w = tid >> 5;
    const int l = tid & 31;                          // local gate row
    const int c0 = blockIdx.x * CPB;
    const int grow = (l >> 3) * HH + c0 + (l & 7);   // global gate row
    const int kb = w * KC;

    // Pre-packed weight pairs: wp[jp] = (W[grow][kb+2jp], W[grow][kb+2jp+1])
    unsigned long long wp[KC / 2];
    {
        const ulonglong2* src = (const ulonglong2*)&Whh[(size_t)grow * HH + kb];
#pragma unroll
        for (int i = 0; i < KC / 4; i++) {
            ulonglong2 v = src[i];
            wp[2 * i] = v.x;
            wp[2 * i + 1] = v.y;
        }
    }

    if (tid < CPB * BB) c_s[tid >> 3][tid & 7] = 0.f;

    // reduce-thread identity + precomputed xg base pointer
    const int rcc = tid >> 3, rb8 = tid & 7;
    const float* xg_base = &g_xg[((size_t)rb8 * TT) * G4 + c0 + rcc];

    for (int t = 0; t < TT; t++) {
        const int rdbuf = t & 1;
        const int wrbuf = rdbuf ^ 1;

        // ---- prefetch this step's xg gate biases (reduce threads) ----
        float xg0, xg1, xg2, xg3;
        if (tid < CPB * BB) {
            const float* p = xg_base + (size_t)t * G4;
            xg0 = __ldcs(p);
            xg1 = __ldcs(p + HH);
            xg2 = __ldcs(p + 2 * HH);
            xg3 = __ldcs(p + 3 * HH);
        }

        // ---- stage h into smem (L2, bypass L1: other CTAs wrote it) ----
        if (t == 0) {
#pragma unroll
            for (int i = tid; i < HH * BB / 4; i += 256)
                ((float4*)h_s)[i] = make_float4(0.f, 0.f, 0.f, 0.f);
        } else {
#pragma unroll
            for (int i = tid; i < HH * BB / 4; i += 256)
                ((float4*)h_s)[i] = __ldcg(((const float4*)g_h[rdbuf]) + i);
        }
        __syncthreads();

        // ---- f32x2 dot partials: row l, k in [kb,kb+128), all 8 batches ----
        unsigned long long acc[BB];   // acc[b] = (even-k sum, odd-k sum)
#pragma unroll
        for (int b = 0; b < BB; b++) acc[b] = 0ull;

        const float* hbase = &h_s[kb * 8];   // pair layout: (kb>>1)*16 == kb*8
#pragma unroll
        for (int jp = 0; jp < KC / 2; jp++) {
            const ulonglong2 h01 = *(const ulonglong2*)&hbase[jp * 16];
            const ulonglong2 h23 = *(const ulonglong2*)&hbase[jp * 16 + 4];
            const ulonglong2 h45 = *(const ulonglong2*)&hbase[jp * 16 + 8];
            const ulonglong2 h67 = *(const ulonglong2*)&hbase[jp * 16 + 12];
            const unsigned long long wv = wp[jp];
            FMA2(acc[0], wv, h01.x); FMA2(acc[1], wv, h01.y);
            FMA2(acc[2], wv, h23.x); FMA2(acc[3], wv, h23.y);
            FMA2(acc[4], wv, h45.x); FMA2(acc[5], wv, h45.y);
            FMA2(acc[6], wv, h67.x); FMA2(acc[7], wv, h67.y);
        }
#pragma unroll
        for (int b = 0; b < BB; b++) {
            float2 f = *(float2*)&acc[b];
            part[w][l][b] = f.x + f.y;
        }
        __syncthreads();

        // ---- gate reduce + nonlinearity + state update (64 threads) ----
        if (tid < CPB * BB) {
            float g0 = xg0, g1 = xg1, g2 = xg2, g3 = xg3;
#pragma unroll
            for (int ww = 0; ww < 8; ww++) {
                g0 += part[ww][0 * 8 + rcc][rb8];
                g1 += part[ww][1 * 8 + rcc][rb8];
                g2 += part[ww][2 * 8 + rcc][rb8];
                g3 += part[ww][3 * 8 + rcc][rb8];
            }
            const float ig = 1.f / (1.f + expf(-g0));
            const float fg = 1.f / (1.f + expf(-g1));
            const float gg = tanhf(g2);
            const float og = 1.f / (1.f + expf(-g3));
            const float c = fg * c_s[rcc][rb8] + ig * gg;
            c_s[rcc][rb8] = c;
            const float h = og * tanhf(c);
            const int col = c0 + rcc;
            g_h[wrbuf][(col >> 1) * 16 + rb8 * 2 + (col & 1)] = h;
        }
        __syncthreads();

        // ---- grid-wide sense barrier ----
        if (tid == 0) {
            __threadfence();
            const unsigned int target = (unsigned int)(t + 1);
            if (atomicAdd(&g_bar_count, 1) == NB - 1) {
                g_bar_count = 0;
                __threadfence();
                g_bar_sense = target;
            } else {
                while (g_bar_sense != target) { }
            }
            __threadfence();
        }
        __syncthreads();
    }
}

// =================================================================
// Kernel 3: out[b][o] = sum_k hT[b][k]*W_fc[o][k] + b_fc[o]
//   hT in g_h[0] (pair layout) after 2048 steps.
// =================================================================
__global__ __launch_bounds__(256) void fc_kernel(
    const float* __restrict__ Wfc, const float* __restrict__ bfc,
    float* __restrict__ out)
{
    const int o = blockIdx.x;
    const int tid = threadIdx.x;
    float acc[BB];
#pragma unroll
    for (int b = 0; b < BB; b++) acc[b] = 0.f;

    for (int k = tid; k < HH; k += 256) {
        const float wv = Wfc[(size_t)o * HH + k];
        const int base = (k >> 1) * 16 + (k & 1);
#pragma unroll
        for (int b = 0; b < BB; b++) acc[b] += wv * g_h[0][base + b * 2];
    }
    const int lane = tid & 31, wrp = tid >> 5;
#pragma unroll
    for (int off = 16; off; off >>= 1)
#pragma unroll
        for (int b = 0; b < BB; b++)
            acc[b] += __shfl_down_sync(0xffffffffu, acc[b], off);

    __shared__ float red[8][BB];
    if (lane == 0)
#pragma unroll
        for (int b = 0; b < BB; b++) red[wrp][b] = acc[b];
    __syncthreads();
    if (tid < BB) {
        float s = bfc[o];
#pragma unroll
        for (int ww = 0; ww < 8; ww++) s += red[ww][tid];
        out[(size_t)tid * OO + o] = s;
    }
}

// =================================================================
extern "C" void kernel_launch(void* const* d_in, const int* in_sizes, int n_in,
                              void* d_out, int out_size)
{
    const float* x    = (const float*)d_in[0];   // [8,2048,1024]
    const float* Wih  = (const float*)d_in[1];   // [4096,1024]
    const float* Whh  = (const float*)d_in[2];   // [4096,1024]
    const float* bih  = (const float*)d_in[3];   // [4096]
    const float* bhh  = (const float*)d_in[4];   // [4096]
    const float* Wfc  = (const float*)d_in[5];   // [4096,1024]
    const float* bfc  = (const float*)d_in[6];   // [4096]
    float* out = (float*)d_out;                  // [1,8,4096]

    dim3 g1(G4 / BN, (BB * TT) / BM);            // (32, 128)
    gemm_xg_kernel<<<g1, 256>>>(x, Wih, bih, bhh);
    lstm_rec_kernel<<<NB, 256>>>(Whh);
    fc_kernel<<<OO, 256>>>(Wfc, bfc, out);
    (void)in_sizes; (void)n_in; (void)out_size;
}

// round 3
// speedup vs baseline: 1.1430x; 1.0021x over previous
#include <cuda_runtime.h>
#include <math.h>

#define BB 8
#define TT 2048
#define II 1024
#define HH 1024
#define G4 4096
#define OO 4096

// ---------------- scratch (no allocations allowed) ----------------
__device__ float g_xg[(size_t)BB * TT * G4];   // [b][t][4H] input-gate precompute
__device__ float g_h[2][HH * BB];              // double-buffered h, PAIR layout:
                                               //   (k,b) -> (k>>1)*16 + b*2 + (k&1)
#define NB 128
__device__ volatile unsigned int g_flags[NB * 32];  // one 128B line per CTA
__device__ volatile unsigned int g_sense;

// packed f32x2 helpers (sm_103a: fma.rn.f32x2 only reachable via PTX)
#define FMA2(d, a, b) asm("fma.rn.f32x2 %0, %1, %2, %0;" : "+l"(d) : "l"(a), "l"(b))
#define PACK2(d, s)   asm("mov.b64 %0, {%1, %1};" : "=l"(d) : "f"(s))

__device__ __forceinline__ float tanh_fast(float x) {
    float y; asm("tanh.approx.f32 %0, %1;" : "=f"(y) : "f"(x)); return y;
}
__device__ __forceinline__ float sigmoid_fast(float x) {
    return 0.5f + 0.5f * tanh_fast(0.5f * x);
}

// =================================================================
// Kernel 1: xg[m][n] = sum_k x[m][k]*W_ih[n][k] + (b_ih[n]+b_hh[n])
//   (unchanged from R1 — measured ~f32x2 pipe-bound)
// =================================================================
#define BM 128
#define BN 128
#define BK 16
#define LDP 132

__global__ __launch_bounds__(256) void gemm_xg_kernel(
    const float* __restrict__ x, const float* __restrict__ Wih,
    const float* __restrict__ bih, const float* __restrict__ bhh)
{
    __shared__ float As[BK][LDP];
    __shared__ float Ws[BK][LDP];
    const int tid = threadIdx.x;
    const int m0 = blockIdx.y * BM;
    const int n0 = blockIdx.x * BN;
    const int tx = tid & 15;
    const int ty = tid >> 4;

    unsigned long long acc[4][8];
#pragma unroll
    for (int p = 0; p < 4; p++)
#pragma unroll
        for (int n = 0; n < 8; n++) acc[p][n] = 0ull;

    for (int k0 = 0; k0 < II; k0 += BK) {
#pragma unroll
        for (int r = 0; r < 2; r++) {
            int f = tid + r * 256;
            int m = f >> 2, kq = f & 3;
            float4 v = *(const float4*)&x[(size_t)(m0 + m) * II + k0 + kq * 4];
            As[kq * 4 + 0][m] = v.x;
            As[kq * 4 + 1][m] = v.y;
            As[kq * 4 + 2][m] = v.z;
            As[kq * 4 + 3][m] = v.w;
        }
#pragma unroll
        for (int r = 0; r < 2; r++) {
            int f = tid + r * 256;
            int n = f >> 2, kq = f & 3;
            float4 v = *(const float4*)&Wih[(size_t)(n0 + n) * II + k0 + kq * 4];
            Ws[kq * 4 + 0][n] = v.x;
            Ws[kq * 4 + 1][n] = v.y;
            Ws[kq * 4 + 2][n] = v.z;
            Ws[kq * 4 + 3][n] = v.w;
        }
        __syncthreads();
#pragma unroll
        for (int kk = 0; kk < BK; kk++) {
            const ulonglong2 a01 = *(const ulonglong2*)&As[kk][ty * 8];
            const ulonglong2 a23 = *(const ulonglong2*)&As[kk][ty * 8 + 4];
            const float4 w0 = *(const float4*)&Ws[kk][tx * 8];
            const float4 w1 = *(const float4*)&Ws[kk][tx * 8 + 4];
            unsigned long long wd[8];
            PACK2(wd[0], w0.x); PACK2(wd[1], w0.y);
            PACK2(wd[2], w0.z); PACK2(wd[3], w0.w);
            PACK2(wd[4], w1.x); PACK2(wd[5], w1.y);
            PACK2(wd[6], w1.z); PACK2(wd[7], w1.w);
#pragma unroll
            for (int n = 0; n < 8; n++) {
                FMA2(acc[0][n], a01.x, wd[n]);
                FMA2(acc[1][n], a01.y, wd[n]);
                FMA2(acc[2][n], a23.x, wd[n]);
                FMA2(acc[3][n], a23.y, wd[n]);
            }
        }
        __syncthreads();
    }

    float bias[8];
#pragma unroll
    for (int n = 0; n < 8; n++) {
        int nn = n0 + tx * 8 + n;
        bias[n] = bih[nn] + bhh[nn];
    }
#pragma unroll
    for (int p = 0; p < 4; p++) {
        float r0[8], r1[8];
#pragma unroll
        for (int n = 0; n < 8; n++) {
            float2 f = *(float2*)&acc[p][n];
            r0[n] = f.x + bias[n];
            r1[n] = f.y + bias[n];
        }
        const size_t m = (size_t)(m0 + ty * 8 + 2 * p);
        float* o0 = &g_xg[m * G4 + n0 + tx * 8];
        float* o1 = o0 + G4;
        *(float4*)o0       = make_float4(r0[0], r0[1], r0[2], r0[3]);
        *((float4*)o0 + 1) = make_float4(r0[4], r0[5], r0[6], r0[7]);
        *(float4*)o1       = make_float4(r1[0], r1[1], r1[2], r1[3]);
        *((float4*)o1 + 1) = make_float4(r1[4], r1[5], r1[6], r1[7]);
    }
}

// =================================================================
// Kernel 2: persistent recurrent LSTM. 128 CTAs x 256 thr, 1 CTA/SM.
//   - distributed-arrival barrier (per-CTA flag lines + CTA0 collector)
//   - per-warp h staging (own k-chunk only, __syncwarp not __syncthreads)
//   - MUFU tanh.approx tail
// =================================================================
#define CPB 8     // h columns per block
#define KC 128    // k elements per warp

__global__ __launch_bounds__(256, 1) void lstm_rec_kernel(const float* __restrict__ Whh)
{
    __shared__ float h_s[HH * BB];          // 32 KB, pair layout
    __shared__ float part[8][32][9];        // [warp][local row][b] pad 9: conflict-free
    __shared__ float c_s[CPB][BB];          // cell state

    const int tid = threadIdx.x;
    const int w = tid >> 5;
    const int l = tid & 31;                          // local gate row
    const int bid = blockIdx.x;
    const int c0 = bid * CPB;
    const int grow = (l >> 3) * HH + c0 + (l & 7);   // global gate row
    const int kb = w * KC;

    // Pre-packed weight pairs: wp[jp] = (W[grow][kb+2jp], W[grow][kb+2jp+1])
    unsigned long long wp[KC / 2];
    {
        const ulonglong2* src = (const ulonglong2*)&Whh[(size_t)grow * HH + kb];
#pragma unroll
        for (int i = 0; i < KC / 4; i++) {
            ulonglong2 v = src[i];
            wp[2 * i] = v.x;
            wp[2 * i + 1] = v.y;
        }
    }

    if (tid < CPB * BB) c_s[tid >> 3][tid & 7] = 0.f;
    __syncthreads();

    // reduce-thread identity + precomputed xg base pointer
    const int rcc = tid >> 3, rb8 = tid & 7;
    const float* xg_base = &g_xg[((size_t)rb8 * TT) * G4 + c0 + rcc];

    // this warp's h chunk staging pointers (pair layout: kb*8 floats offset)
    float4* hchunk = (float4*)&h_s[kb * 8];          // 256 float4 per warp

    for (int t = 0; t < TT; t++) {
        const int rdbuf = t & 1;
        const int wrbuf = rdbuf ^ 1;

        // ---- prefetch this step's xg gate biases (reduce threads) ----
        float xg0, xg1, xg2, xg3;
        if (tid < CPB * BB) {
            const float* p = xg_base + (size_t)t * G4;
            xg0 = __ldcs(p);
            xg1 = __ldcs(p + HH);
            xg2 = __ldcs(p + 2 * HH);
            xg3 = __ldcs(p + 3 * HH);
        }

        // ---- per-warp stage of OWN h chunk (L2 read; own-warp visibility) ----
        if (t == 0) {
#pragma unroll
            for (int i = l; i < 256; i += 32)
                hchunk[i] = make_float4(0.f, 0.f, 0.f, 0.f);
        } else {
            const float4* src = (const float4*)&g_h[rdbuf][kb * 8];
#pragma unroll
            for (int i = l; i < 256; i += 32)
                hchunk[i] = __ldcg(src + i);
        }
        __syncwarp();

        // ---- f32x2 dot partials: row l, k in [kb,kb+128), all 8 batches ----
        unsigned long long acc[BB];
#pragma unroll
        for (int b = 0; b < BB; b++) acc[b] = 0ull;

        const float* hbase = &h_s[kb * 8];
#pragma unroll
        for (int jp = 0; jp < KC / 2; jp++) {
            const ulonglong2 h01 = *(const ulonglong2*)&hbase[jp * 16];
            const ulonglong2 h23 = *(const ulonglong2*)&hbase[jp * 16 + 4];
            const ulonglong2 h45 = *(const ulonglong2*)&hbase[jp * 16 + 8];
            const ulonglong2 h67 = *(const ulonglong2*)&hbase[jp * 16 + 12];
            const unsigned long long wv = wp[jp];
            FMA2(acc[0], wv, h01.x); FMA2(acc[1], wv, h01.y);
            FMA2(acc[2], wv, h23.x); FMA2(acc[3], wv, h23.y);
            FMA2(acc[4], wv, h45.x); FMA2(acc[5], wv, h45.y);
            FMA2(acc[6], wv, h67.x); FMA2(acc[7], wv, h67.y);
        }
#pragma unroll
        for (int b = 0; b < BB; b++) {
            float2 f = *(float2*)&acc[b];
            part[w][l][b] = f.x + f.y;
        }
        __syncthreads();

        // ---- gate reduce + MUFU nonlinearity + state update (64 threads) ----
        if (tid < CPB * BB) {
            float g0 = xg0, g1 = xg1, g2 = xg2, g3 = xg3;
#pragma unroll
            for (int ww = 0; ww < 8; ww++) {
                g0 += part[ww][0 * 8 + rcc][rb8];
                g1 += part[ww][1 * 8 + rcc][rb8];
                g2 += part[ww][2 * 8 + rcc][rb8];
                g3 += part[ww][3 * 8 + rcc][rb8];
            }
            const float ig = sigmoid_fast(g0);
            const float fg = sigmoid_fast(g1);
            const float gg = tanh_fast(g2);
            const float og = sigmoid_fast(g3);
            const float c = fg * c_s[rcc][rb8] + ig * gg;
            c_s[rcc][rb8] = c;
            const float h = og * tanh_fast(c);
            const int col = c0 + rcc;
            g_h[wrbuf][(col >> 1) * 16 + rb8 * 2 + (col & 1)] = h;
        }
        __syncthreads();   // h writes done CTA-wide; part[] safe to reuse

        // ---- grid barrier: distributed arrival, CTA0 collects, 1-word release --
        const unsigned int tgt = (unsigned int)(t + 1);
        if (tid == 0) {
            __threadfence();
            g_flags[bid * 32] = tgt;
        }
        if (bid == 0) {
            if (tid < NB) {
                while (g_flags[tid * 32] != tgt) { }
            }
            __syncthreads();
            if (tid == 0) {
                __threadfence();
                g_sense = tgt;
            }
        } else {
            if (tid == 0) {
                while (g_sense != tgt) { }
                __threadfence();
            }
            __syncthreads();
        }
    }
}

// =================================================================
// Kernel 3: out[b][o] = sum_k hT[b][k]*W_fc[o][k] + b_fc[o]
// =================================================================
__global__ __launch_bounds__(256) void fc_kernel(
    const float* __restrict__ Wfc, const float* __restrict__ bfc,
    float* __restrict__ out)
{
    const int o = blockIdx.x;
    const int tid = threadIdx.x;
    float acc[BB];
#pragma unroll
    for (int b = 0; b < BB; b++) acc[b] = 0.f;

    for (int k = tid; k < HH; k += 256) {
        const float wv = Wfc[(size_t)o * HH + k];
        const int base = (k >> 1) * 16 + (k & 1);
#pragma unroll
        for (int b = 0; b < BB; b++) acc[b] += wv * g_h[0][base + b * 2];
    }
    const int lane = tid & 31, wrp = tid >> 5;
#pragma unroll
    for (int off = 16; off; off >>= 1)
#pragma unroll
        for (int b = 0; b < BB; b++)
            acc[b] += __shfl_down_sync(0xffffffffu, acc[b], off);

    __shared__ float red[8][BB];
    if (lane == 0)
#pragma unroll
        for (int b = 0; b < BB; b++) red[wrp][b] = acc[b];
    __syncthreads();
    if (tid < BB) {
        float s = bfc[o];
#pragma unroll
        for (int ww = 0; ww < 8; ww++) s += red[ww][tid];
        out[(size_t)tid * OO + o] = s;
    }
}

// =================================================================
extern "C" void kernel_launch(void* const* d_in, const int* in_sizes, int n_in,
                              void* d_out, int out_size)
{
    const float* x    = (const float*)d_in[0];
    const float* Wih  = (const float*)d_in[1];
    const float* Whh  = (const float*)d_in[2];
    const float* bih  = (const float*)d_in[3];
    const float* bhh  = (const float*)d_in[4];
    const float* Wfc  = (const float*)d_in[5];
    const float* bfc  = (const float*)d_in[6];
    float* out = (float*)d_out;

    dim3 g1(G4 / BN, (BB * TT) / BM);
    gemm_xg_kernel<<<g1, 256>>>(x, Wih, bih, bhh);
    lstm_rec_kernel<<<NB, 256>>>(Whh);
    fc_kernel<<<OO, 256>>>(Wfc, bfc, out);
    (void)in_sizes; (void)n_in; (void)out_size;
}